// round 6
// baseline (speedup 1.0000x reference)
#include <cuda_runtime.h>

// Problem constants
#define NN 50000      // nodes
#define FF 64         // features
#define HH 2          // heads
#define EE 800000     // edges
#define CC 256        // 2*H*F projected columns per node
#define SLOTS 128     // per-row edge bin capacity (expected max degree ~35)

// Device scratch (static globals — no runtime allocation)
__device__ float g_qk[(size_t)NN * CC];          // [N,256]: h0:q(64)|k(64), h1:q(64)|k(64)
__device__ int   g_cnt[NN];                      // per-row edge counts / cursors
__device__ int2  g_slots[(size_t)NN * SLOTS];    // per-row bins: (col, edge_id)

// ---------------------------------------------------------------------------
// Kernel 1: qk = x @ W + b   ([N,64] @ [64,256] -> [N,256])
// 256 threads/block; thread j owns output column j. W column j held as
// 32 f32x2 pairs (64 regs) paired along f. x tile (64 nodes x 64 f) staged
// in static smem as u64 pairs (natural adjacent-f pairs; base 16B-aligned,
// all offsets even-u64 -> any LDS merge is alignment-safe). 4 nodes in
// flight = 4 independent FFMA2 accumulator chains. All x loads in the hot
// loop are warp-broadcast (index independent of threadIdx).
// ---------------------------------------------------------------------------
#define NODES_PER_BLOCK 64

__global__ __launch_bounds__(256) void gemm_kernel(
    const float* __restrict__ x,
    const float* __restrict__ W,
    const float* __restrict__ b)
{
    __shared__ __align__(16) unsigned long long xs[NODES_PER_BLOCK * (FF / 2)]; // 16 KB

    const int j = threadIdx.x;                   // output column 0..255
    const int node0 = blockIdx.x * NODES_PER_BLOCK;

    // W column j as 32 f32x2 pairs along f (coalesced gmem reads across j)
    unsigned long long wp[FF / 2];
#pragma unroll
    for (int p = 0; p < FF / 2; p++) {
        float a0 = W[(2 * p) * CC + j];
        float a1 = W[(2 * p + 1) * CC + j];
        asm("mov.b64 %0, {%1,%2};" : "=l"(wp[p]) : "f"(a0), "f"(a1));
    }
    const float bj = b[j];

    // stage x tile (coalesced float4 loads; same bytes reinterpreted as u64 pairs)
    const int nmax = min(NODES_PER_BLOCK, NN - node0);   // 64, or 16 on last tile
    const int nf4 = nmax * (FF / 4);
    const float4* x4 = reinterpret_cast<const float4*>(x + (size_t)node0 * FF);
    float4* xs4 = reinterpret_cast<float4*>(xs);
    for (int idx = j; idx < nf4; idx += 256) xs4[idx] = x4[idx];
    __syncthreads();

    // NN % NODES_PER_BLOCK == 16, so nmax is always a multiple of 4
    for (int n0 = 0; n0 < nmax; n0 += 4) {
        unsigned long long acc[4];
#pragma unroll
        for (int k = 0; k < 4; k++) acc[k] = 0ull;

#pragma unroll 8
        for (int p = 0; p < FF / 2; p++) {
#pragma unroll
            for (int k = 0; k < 4; k++) {
                asm("fma.rn.f32x2 %0, %1, %2, %0;"
                    : "+l"(acc[k])
                    : "l"(xs[(n0 + k) * (FF / 2) + p]), "l"(wp[p]));
            }
        }

#pragma unroll
        for (int k = 0; k < 4; k++) {
            float lo, hi;
            asm("mov.b64 {%0,%1}, %2;" : "=f"(lo), "=f"(hi) : "l"(acc[k]));
            g_qk[(size_t)(node0 + n0 + k) * CC + j] = lo + hi + bj;  // coalesced
        }
    }
}

// ---------------------------------------------------------------------------
// Kernel 2: bucket edges by source row (order within a row irrelevant)
// ---------------------------------------------------------------------------
__global__ __launch_bounds__(256) void scatter_kernel(const int* __restrict__ ei)
{
    int e = blockIdx.x * blockDim.x + threadIdx.x;
    if (e >= EE) return;
    int row = ei[e];
    int col = ei[EE + e];
    int pos = atomicAdd(&g_cnt[row], 1);
    if (pos < SLOTS)
        g_slots[(size_t)row * SLOTS + pos] = make_int2(col, e);
}

// ---------------------------------------------------------------------------
// Kernel 3 (exact R3-passing version): one warp per row, 4 edges in flight.
// Lane decomposition: sub = lane>>4 (edge of pair), h = (lane>>3)&1 (head),
// c = lane&7 (8-float chunk). 8 lanes per (edge,head); 3-shfl reduction.
// ---------------------------------------------------------------------------
__global__ __launch_bounds__(256) void row_kernel(float* __restrict__ out)
{
    __shared__ float exbuf[8][SLOTS][2];         // 8 KB

    const int w    = threadIdx.x >> 5;
    const int lane = threadIdx.x & 31;
    const int row  = blockIdx.x * 8 + w;
    if (row >= NN) return;

    const int sub = lane >> 4;                   // which edge of the pair
    const int h   = (lane >> 3) & 1;             // head
    const int c   = lane & 7;                    // chunk of 8 floats

    const float4* qp = reinterpret_cast<const float4*>(
        g_qk + (size_t)row * CC + h * 128 + c * 8);
    const float4 qa = qp[0];
    const float4 qb = qp[1];

    int deg = g_cnt[row];
    if (deg > SLOTS) deg = SLOTS;
    const int2* sl = g_slots + (size_t)row * SLOTS;

    float denom = 0.0f;                          // valid on lanes 0, 8, 16, 24

    for (int i0 = 0; i0 < deg; i0 += 4) {
        const int iA = i0 + sub;
        const int iB = i0 + 2 + sub;
        const bool vA = iA < deg;
        const bool vB = iB < deg;
        const int colA = vA ? sl[iA].x : 0;
        const int colB = vB ? sl[iB].x : 0;

        const float4* kA = reinterpret_cast<const float4*>(
            g_qk + (size_t)colA * CC + h * 128 + 64 + c * 8);
        const float4* kB = reinterpret_cast<const float4*>(
            g_qk + (size_t)colB * CC + h * 128 + 64 + c * 8);
        float4 ka0 = kA[0], ka1 = kA[1];
        float4 kb0 = kB[0], kb1 = kB[1];

        float sA = qa.x * ka0.x + qa.y * ka0.y + qa.z * ka0.z + qa.w * ka0.w
                 + qb.x * ka1.x + qb.y * ka1.y + qb.z * ka1.z + qb.w * ka1.w;
        float sB = qa.x * kb0.x + qa.y * kb0.y + qa.z * kb0.z + qa.w * kb0.w
                 + qb.x * kb1.x + qb.y * kb1.y + qb.z * kb1.z + qb.w * kb1.w;

        sA += __shfl_xor_sync(0xffffffffu, sA, 1);
        sB += __shfl_xor_sync(0xffffffffu, sB, 1);
        sA += __shfl_xor_sync(0xffffffffu, sA, 2);
        sB += __shfl_xor_sync(0xffffffffu, sB, 2);
        sA += __shfl_xor_sync(0xffffffffu, sA, 4);
        sB += __shfl_xor_sync(0xffffffffu, sB, 4);

        if (c == 0) {
            if (vA) {
                float ex = __expf(sA);           // |s| <~ 15: no max-shift needed
                exbuf[w][iA][h] = ex;
                denom += ex;
            }
            if (vB) {
                float ex = __expf(sB);
                exbuf[w][iB][h] = ex;
                denom += ex;
            }
        }
    }

    float d0 = __shfl_sync(0xffffffffu, denom, 0)
             + __shfl_sync(0xffffffffu, denom, 16);   // head 0
    float d1 = __shfl_sync(0xffffffffu, denom, 8)
             + __shfl_sync(0xffffffffu, denom, 24);   // head 1
    float c0 = 0.5f / d0;
    float c1 = 0.5f / d1;
    __syncwarp();

    for (int i = lane; i < deg; i += 32) {
        int2 sc = sl[i];
        out[sc.y] = exbuf[w][i][0] * c0 + exbuf[w][i][1] * c1;
    }
}

// ---------------------------------------------------------------------------
extern "C" void kernel_launch(void* const* d_in, const int* in_sizes, int n_in,
                              void* d_out, int out_size)
{
    const float* x   = (const float*)d_in[0];    // [50000, 64]
    const float* W   = (const float*)d_in[1];    // [64, 256]
    const float* b   = (const float*)d_in[2];    // [256]
    const int*   ei  = (const int*)  d_in[3];    // [2, 800000]
    float*       out = (float*)d_out;            // [800000]

    (void)in_sizes; (void)n_in; (void)out_size;

    // zero the row cursors (graph-capturable async memset; passed in R3)
    void* cnt_ptr = nullptr;
    cudaGetSymbolAddress(&cnt_ptr, g_cnt);
    cudaMemsetAsync(cnt_ptr, 0, NN * sizeof(int));

    gemm_kernel<<<(NN + NODES_PER_BLOCK - 1) / NODES_PER_BLOCK, 256>>>(x, W, b);
    scatter_kernel<<<(EE + 255) / 256, 256>>>(ei);
    row_kernel<<<(NN + 7) / 8, 256>>>(out);
}

// round 7
// speedup vs baseline: 1.3106x; 1.3106x over previous
#include <cuda_runtime.h>

// Problem constants
#define NN 50000      // nodes
#define FF 64         // features
#define HH 2          // heads
#define EE 800000     // edges
#define CC 256        // 2*H*F projected columns per node
#define SLOTS 128     // per-row edge bin capacity (expected max degree ~35)

// Device scratch (static globals — no runtime allocation)
__device__ float g_qk[(size_t)NN * CC];          // [N,256]: h0:q(64)|k(64), h1:q(64)|k(64)
__device__ int   g_cnt[NN];                      // per-row edge counts / cursors
__device__ int2  g_slots[(size_t)NN * SLOTS];    // per-row bins: (col, edge_id)

// ---------------------------------------------------------------------------
// Kernel 1: qk = x @ W + b   ([N,64] @ [64,256] -> [N,256])
// 256 threads/block; thread j owns output column j. W column j held as
// 32 f32x2 pairs (64 regs, f-adjacent pairs). x tile staged in static smem
// as u64 pairs; all hot-loop x loads are warp-broadcast LDS.64.
// 4 nodes in flight = 4 independent FFMA2 chains.
// CRITICAL (R6 lesson): the p-loop must be FULLY unrolled so every wp[p]
// index is compile-time constant — partial unroll demoted wp[] to local
// memory (regs=40, LDL-bound, 2x slower).
// ---------------------------------------------------------------------------
#define NODES_PER_BLOCK 64

__global__ __launch_bounds__(256) void gemm_kernel(
    const float* __restrict__ x,
    const float* __restrict__ W,
    const float* __restrict__ b)
{
    __shared__ __align__(16) unsigned long long xs[NODES_PER_BLOCK * (FF / 2)]; // 16 KB

    const int j = threadIdx.x;                   // output column 0..255
    const int node0 = blockIdx.x * NODES_PER_BLOCK;

    // W column j as 32 f32x2 pairs along f (coalesced gmem reads across j)
    unsigned long long wp[FF / 2];
#pragma unroll
    for (int p = 0; p < FF / 2; p++) {
        float a0 = W[(2 * p) * CC + j];
        float a1 = W[(2 * p + 1) * CC + j];
        asm("mov.b64 %0, {%1,%2};" : "=l"(wp[p]) : "f"(a0), "f"(a1));
    }
    const float bj = b[j];

    // stage x tile (coalesced float4 loads; same bytes reinterpreted as u64 pairs)
    const int nmax = min(NODES_PER_BLOCK, NN - node0);   // 64, or 16 on last tile
    const int nf4 = nmax * (FF / 4);
    const float4* x4 = reinterpret_cast<const float4*>(x + (size_t)node0 * FF);
    float4* xs4 = reinterpret_cast<float4*>(xs);
    for (int idx = j; idx < nf4; idx += 256) xs4[idx] = x4[idx];
    __syncthreads();

    // NN % NODES_PER_BLOCK == 16, so nmax is always a multiple of 4
    for (int n0 = 0; n0 < nmax; n0 += 4) {
        unsigned long long acc0 = 0ull, acc1 = 0ull, acc2 = 0ull, acc3 = 0ull;
        const unsigned long long* xr = &xs[n0 * (FF / 2)];

#pragma unroll
        for (int p = 0; p < FF / 2; p++) {       // FULL unroll: wp[p] const index
            asm("fma.rn.f32x2 %0, %1, %2, %0;"
                : "+l"(acc0) : "l"(xr[p]), "l"(wp[p]));
            asm("fma.rn.f32x2 %0, %1, %2, %0;"
                : "+l"(acc1) : "l"(xr[(FF / 2) + p]), "l"(wp[p]));
            asm("fma.rn.f32x2 %0, %1, %2, %0;"
                : "+l"(acc2) : "l"(xr[2 * (FF / 2) + p]), "l"(wp[p]));
            asm("fma.rn.f32x2 %0, %1, %2, %0;"
                : "+l"(acc3) : "l"(xr[3 * (FF / 2) + p]), "l"(wp[p]));
        }

        float lo, hi;
        asm("mov.b64 {%0,%1}, %2;" : "=f"(lo), "=f"(hi) : "l"(acc0));
        g_qk[(size_t)(node0 + n0 + 0) * CC + j] = lo + hi + bj;
        asm("mov.b64 {%0,%1}, %2;" : "=f"(lo), "=f"(hi) : "l"(acc1));
        g_qk[(size_t)(node0 + n0 + 1) * CC + j] = lo + hi + bj;
        asm("mov.b64 {%0,%1}, %2;" : "=f"(lo), "=f"(hi) : "l"(acc2));
        g_qk[(size_t)(node0 + n0 + 2) * CC + j] = lo + hi + bj;
        asm("mov.b64 {%0,%1}, %2;" : "=f"(lo), "=f"(hi) : "l"(acc3));
        g_qk[(size_t)(node0 + n0 + 3) * CC + j] = lo + hi + bj;
    }
}

// ---------------------------------------------------------------------------
// Kernel 2: bucket edges by source row (order within a row irrelevant)
// ---------------------------------------------------------------------------
__global__ __launch_bounds__(256) void scatter_kernel(const int* __restrict__ ei)
{
    int e = blockIdx.x * blockDim.x + threadIdx.x;
    if (e >= EE) return;
    int row = ei[e];
    int col = ei[EE + e];
    int pos = atomicAdd(&g_cnt[row], 1);
    if (pos < SLOTS)
        g_slots[(size_t)row * SLOTS + pos] = make_int2(col, e);
}

// ---------------------------------------------------------------------------
// Kernel 3 (R3-passing version, measured 52us): one warp per row, 4 edges
// in flight. sub = lane>>4 (edge of pair), h = (lane>>3)&1 (head),
// c = lane&7 (8-float chunk). 8 lanes per (edge,head); 3-shfl reduction.
// ---------------------------------------------------------------------------
__global__ __launch_bounds__(256) void row_kernel(float* __restrict__ out)
{
    __shared__ float exbuf[8][SLOTS][2];         // 8 KB

    const int w    = threadIdx.x >> 5;
    const int lane = threadIdx.x & 31;
    const int row  = blockIdx.x * 8 + w;
    if (row >= NN) return;

    const int sub = lane >> 4;                   // which edge of the pair
    const int h   = (lane >> 3) & 1;             // head
    const int c   = lane & 7;                    // chunk of 8 floats

    const float4* qp = reinterpret_cast<const float4*>(
        g_qk + (size_t)row * CC + h * 128 + c * 8);
    const float4 qa = qp[0];
    const float4 qb = qp[1];

    int deg = g_cnt[row];
    if (deg > SLOTS) deg = SLOTS;
    const int2* sl = g_slots + (size_t)row * SLOTS;

    float denom = 0.0f;                          // valid on lanes 0, 8, 16, 24

    for (int i0 = 0; i0 < deg; i0 += 4) {
        const int iA = i0 + sub;
        const int iB = i0 + 2 + sub;
        const bool vA = iA < deg;
        const bool vB = iB < deg;
        const int colA = vA ? sl[iA].x : 0;
        const int colB = vB ? sl[iB].x : 0;

        const float4* kA = reinterpret_cast<const float4*>(
            g_qk + (size_t)colA * CC + h * 128 + 64 + c * 8);
        const float4* kB = reinterpret_cast<const float4*>(
            g_qk + (size_t)colB * CC + h * 128 + 64 + c * 8);
        float4 ka0 = kA[0], ka1 = kA[1];
        float4 kb0 = kB[0], kb1 = kB[1];

        float sA = qa.x * ka0.x + qa.y * ka0.y + qa.z * ka0.z + qa.w * ka0.w
                 + qb.x * ka1.x + qb.y * ka1.y + qb.z * ka1.z + qb.w * ka1.w;
        float sB = qa.x * kb0.x + qa.y * kb0.y + qa.z * kb0.z + qa.w * kb0.w
                 + qb.x * kb1.x + qb.y * kb1.y + qb.z * kb1.z + qb.w * kb1.w;

        sA += __shfl_xor_sync(0xffffffffu, sA, 1);
        sB += __shfl_xor_sync(0xffffffffu, sB, 1);
        sA += __shfl_xor_sync(0xffffffffu, sA, 2);
        sB += __shfl_xor_sync(0xffffffffu, sB, 2);
        sA += __shfl_xor_sync(0xffffffffu, sA, 4);
        sB += __shfl_xor_sync(0xffffffffu, sB, 4);

        if (c == 0) {
            if (vA) {
                float ex = __expf(sA);           // |s| <~ 15: no max-shift needed
                exbuf[w][iA][h] = ex;
                denom += ex;
            }
            if (vB) {
                float ex = __expf(sB);
                exbuf[w][iB][h] = ex;
                denom += ex;
            }
        }
    }

    float d0 = __shfl_sync(0xffffffffu, denom, 0)
             + __shfl_sync(0xffffffffu, denom, 16);   // head 0
    float d1 = __shfl_sync(0xffffffffu, denom, 8)
             + __shfl_sync(0xffffffffu, denom, 24);   // head 1
    float c0 = 0.5f / d0;
    float c1 = 0.5f / d1;
    __syncwarp();

    for (int i = lane; i < deg; i += 32) {
        int2 sc = sl[i];
        out[sc.y] = exbuf[w][i][0] * c0 + exbuf[w][i][1] * c1;
    }
}

// ---------------------------------------------------------------------------
extern "C" void kernel_launch(void* const* d_in, const int* in_sizes, int n_in,
                              void* d_out, int out_size)
{
    const float* x   = (const float*)d_in[0];    // [50000, 64]
    const float* W   = (const float*)d_in[1];    // [64, 256]
    const float* b   = (const float*)d_in[2];    // [256]
    const int*   ei  = (const int*)  d_in[3];    // [2, 800000]
    float*       out = (float*)d_out;            // [800000]

    (void)in_sizes; (void)n_in; (void)out_size;

    // zero the row cursors (graph-capturable async memset)
    void* cnt_ptr = nullptr;
    cudaGetSymbolAddress(&cnt_ptr, g_cnt);
    cudaMemsetAsync(cnt_ptr, 0, NN * sizeof(int));

    gemm_kernel<<<(NN + NODES_PER_BLOCK - 1) / NODES_PER_BLOCK, 256>>>(x, W, b);
    scatter_kernel<<<(EE + 255) / 256, 256>>>(ei);
    row_kernel<<<(NN + 7) / 8, 256>>>(out);
}